// round 12
// baseline (speedup 1.0000x reference)
#include <cuda_runtime.h>
#include <cuda_bf16.h>

// Inputs (metadata order):
//  d_in[0]: local_d_ij                 float32 [16,000,000]
//  d_in[1]: radii_table                float32 [97]
//  d_in[2]: local_pair_indices         int32   [2, 16,000,000] flattened
//  d_in[3]: atomic_numbers             int32   [1,000,000]
//  d_in[4]: atomic_subsystem_indices   int32   [1,000,000]
//  d_out  : per_system energies        float32 [10,000]

#define N_SEG_MAX   10000
#define N_ATOMS_MAX 1000000
#define REPL        16          // scratch replicas to spread atomic contention
#define ZTAB        128         // padded table size (z in 1..96)

static __device__ float g_scratch[REPL * N_SEG_MAX];
static __device__ int   g_packed[N_ATOMS_MAX];   // (seg << 7) | z

__global__ void pack_kernel(const int* __restrict__ z,
                            const int* __restrict__ seg, int n) {
    int i = blockIdx.x * blockDim.x + threadIdx.x;
    if (i < n) g_packed[i] = (seg[i] << 7) | z[i];
}

__global__ void zero_scratch_kernel(int n) {
    int i = blockIdx.x * blockDim.x + threadIdx.x;
    if (i < n) g_scratch[i] = 0.0f;
}

__global__ __launch_bounds__(256)
void edge_kernel(const float* __restrict__ d_ij,
                 const float* __restrict__ radii,
                 const int*   __restrict__ pair_idx,
                 int n_edges, int n_radii) {
    __shared__ float s_rad[ZTAB];
    __shared__ float s_pow[ZTAB];   // z^0.23

    for (int t = threadIdx.x; t < ZTAB; t += blockDim.x) {
        s_rad[t] = (t < n_radii) ? radii[t] : 0.0f;
        s_pow[t] = powf((float)t, 0.23f);
    }
    __syncthreads();

    const double A_PREF_D = 0.8854 * 0.0529177210903;
    const float  INV_A    = (float)(1.0 / A_PREF_D);
    const float  COUL     = 138.9354576f;
    const float  PI_F     = 3.14159265358979f;
    const float  L2E      = 1.44269504088896f;   // log2(e)

    const int4*   ii4 = (const int4*)pair_idx;
    const int4*   jj4 = (const int4*)(pair_idx + n_edges);
    const float4* dd4 = (const float4*)d_ij;

    int n4  = n_edges >> 2;
    int rem = n_edges - (n4 << 2);
    int stride = gridDim.x * blockDim.x;

    // replica: mix block and warp so concurrent warps hit different replicas
    int rep = (blockIdx.x * 8 + (threadIdx.x >> 5)) & (REPL - 1);
    float* sc = g_scratch + rep * N_SEG_MAX;

    for (int e4 = blockIdx.x * blockDim.x + threadIdx.x; e4 < n4; e4 += stride) {
        int4   vi = __ldg(ii4 + e4);
        int4   vj = __ldg(jj4 + e4);
        float4 vd = __ldg(dd4 + e4);

        int   is[4] = {vi.x, vi.y, vi.z, vi.w};
        int   js[4] = {vj.x, vj.y, vj.z, vj.w};
        float ds[4] = {vd.x, vd.y, vd.z, vd.w};

        #pragma unroll
        for (int k = 0; k < 4; k++) {
            int i = is[k], j = js[k];
            if (i >= j) continue;               // mask: idx_i < idx_j
            int pi = __ldg(g_packed + i);
            int pj = __ldg(g_packed + j);
            int zi = pi & 127;
            int zj = pj & 127;
            float d = ds[k];
            float rsum = s_rad[zi] + s_rad[zj];
            if (d >= rsum) continue;            // phi == 0 -> energy == 0

            int   seg = pi >> 7;
            float x   = d * (s_pow[zi] + s_pow[zj]) * INV_A;
            // f = sum of 4 exponentials (exp(-k x) = exp2(-k*log2e*x))
            float f = 0.1818f  * exp2f(-3.2f    * L2E * x)
                    + 0.5099f  * exp2f(-0.9423f * L2E * x)
                    + 0.2802f  * exp2f(-0.4029f * L2E * x)
                    + 0.02817f * exp2f(-0.2016f * L2E * x);
            float phi = 0.5f * (__cosf(PI_F * __fdividef(d, rsum)) + 1.0f);
            float zif = (float)zi, zjf = (float)zj;
            float en  = __fdividef(f * phi * COUL * zif * zjf, d);
            atomicAdd(sc + seg, en);
        }
    }

    // scalar tail (n_edges not divisible by 4) — handled by first few threads
    int base = n4 << 2;
    int t = blockIdx.x * blockDim.x + threadIdx.x;
    if (t < rem) {
        int e = base + t;
        int i = __ldg(pair_idx + e);
        int j = __ldg(pair_idx + n_edges + e);
        if (i < j) {
            int pi = __ldg(g_packed + i);
            int pj = __ldg(g_packed + j);
            int zi = pi & 127, zj = pj & 127;
            float d = __ldg(d_ij + e);
            float rsum = s_rad[zi] + s_rad[zj];
            if (d < rsum) {
                int   seg = pi >> 7;
                float x   = d * (s_pow[zi] + s_pow[zj]) * INV_A;
                float f = 0.1818f  * exp2f(-3.2f    * L2E * x)
                        + 0.5099f  * exp2f(-0.9423f * L2E * x)
                        + 0.2802f  * exp2f(-0.4029f * L2E * x)
                        + 0.02817f * exp2f(-0.2016f * L2E * x);
                float phi = 0.5f * (__cosf(PI_F * __fdividef(d, rsum)) + 1.0f);
                float en  = __fdividef(f * phi * COUL * (float)zi * (float)zj, d);
                atomicAdd(sc + seg, en);
            }
        }
    }
}

__global__ void reduce_kernel(float* __restrict__ out, int n_seg) {
    int s = blockIdx.x * blockDim.x + threadIdx.x;
    if (s < n_seg) {
        float a = 0.0f;
        #pragma unroll
        for (int r = 0; r < REPL; r++) a += g_scratch[r * N_SEG_MAX + s];
        out[s] = a;
    }
}

extern "C" void kernel_launch(void* const* d_in, const int* in_sizes, int n_in,
                              void* d_out, int out_size) {
    const float* d_ij   = (const float*)d_in[0];
    const float* radii  = (const float*)d_in[1];
    const int*   pairs  = (const int*)d_in[2];
    const int*   zs     = (const int*)d_in[3];
    const int*   segs   = (const int*)d_in[4];

    int n_edges = in_sizes[0];
    int n_radii = in_sizes[1];
    int n_atoms = in_sizes[3];
    int n_seg   = out_size;

    // 1. zero the replicated scratch
    {
        int n = REPL * N_SEG_MAX;
        zero_scratch_kernel<<<(n + 255) / 256, 256>>>(n);
    }
    // 2. pack (seg, z) per atom
    pack_kernel<<<(n_atoms + 255) / 256, 256>>>(zs, segs, n_atoms);

    // 3. main edge kernel: 4 edges per thread
    {
        int n4 = n_edges >> 2;
        int threads = 256;
        int blocks = (n4 + threads - 1) / threads;
        if (blocks < 1) blocks = 1;
        edge_kernel<<<blocks, threads>>>(d_ij, radii, pairs, n_edges, n_radii);
    }

    // 4. reduce replicas into output
    reduce_kernel<<<(n_seg + 255) / 256, 256>>>((float*)d_out, n_seg);
}

// round 13
// speedup vs baseline: 1.0141x; 1.0141x over previous
#include <cuda_runtime.h>
#include <cuda_bf16.h>

// Inputs (metadata order):
//  d_in[0]: local_d_ij                 float32 [16,000,000]
//  d_in[1]: radii_table                float32 [97]
//  d_in[2]: local_pair_indices         int32   [2, 16,000,000] flattened
//  d_in[3]: atomic_numbers             int32   [1,000,000]
//  d_in[4]: atomic_subsystem_indices   int32   [1,000,000]
//  d_out  : per_system energies        float32 [10,000]

#define N_SEG_MAX   10000
#define N_ATOMS_MAX 1000000
#define REPL        16          // scratch replicas to spread atomic contention
#define ZTAB        128         // padded table size (z in 1..96)

static __device__ float g_scratch[REPL * N_SEG_MAX];
static __device__ int   g_packed[N_ATOMS_MAX];   // (seg << 7) | z

__global__ void pack_kernel(const int* __restrict__ z,
                            const int* __restrict__ seg, int n) {
    int i = blockIdx.x * blockDim.x + threadIdx.x;
    if (i < n) g_packed[i] = (seg[i] << 7) | z[i];
}

__global__ void zero_scratch_kernel(int n) {
    int i = blockIdx.x * blockDim.x + threadIdx.x;
    if (i < n) g_scratch[i] = 0.0f;
}

__global__ __launch_bounds__(256)
void edge_kernel(const float* __restrict__ d_ij,
                 const float* __restrict__ radii,
                 const int*   __restrict__ pair_idx,
                 int n_edges, int n_radii) {
    __shared__ float s_rad[ZTAB];
    __shared__ float s_pow[ZTAB];   // z^0.23

    for (int t = threadIdx.x; t < ZTAB; t += blockDim.x) {
        s_rad[t] = (t < n_radii) ? radii[t] : 0.0f;
        s_pow[t] = powf((float)t, 0.23f);
    }
    __syncthreads();

    const double A_PREF_D = 0.8854 * 0.0529177210903;
    const float  INV_A    = (float)(1.0 / A_PREF_D);
    const float  COUL     = 138.9354576f;
    const float  PI_F     = 3.14159265358979f;
    const float  L2E      = 1.44269504088896f;   // log2(e)

    const int4*   ii4 = (const int4*)pair_idx;
    const int4*   jj4 = (const int4*)(pair_idx + n_edges);
    const float4* dd4 = (const float4*)d_ij;

    int n4  = n_edges >> 2;
    int rem = n_edges - (n4 << 2);
    int stride = gridDim.x * blockDim.x;

    // replica: mix block and warp so concurrent warps hit different replicas
    int rep = (blockIdx.x * 8 + (threadIdx.x >> 5)) & (REPL - 1);
    float* sc = g_scratch + rep * N_SEG_MAX;

    for (int e4 = blockIdx.x * blockDim.x + threadIdx.x; e4 < n4; e4 += stride) {
        int4   vi = __ldg(ii4 + e4);
        int4   vj = __ldg(jj4 + e4);
        float4 vd = __ldg(dd4 + e4);

        int   is[4] = {vi.x, vi.y, vi.z, vi.w};
        int   js[4] = {vj.x, vj.y, vj.z, vj.w};
        float ds[4] = {vd.x, vd.y, vd.z, vd.w};

        #pragma unroll
        for (int k = 0; k < 4; k++) {
            int i = is[k], j = js[k];
            if (i >= j) continue;               // mask: idx_i < idx_j
            int pi = __ldg(g_packed + i);
            int pj = __ldg(g_packed + j);
            int zi = pi & 127;
            int zj = pj & 127;
            float d = ds[k];
            float rsum = s_rad[zi] + s_rad[zj];
            if (d >= rsum) continue;            // phi == 0 -> energy == 0

            int   seg = pi >> 7;
            float x   = d * (s_pow[zi] + s_pow[zj]) * INV_A;
            // f = sum of 4 exponentials (exp(-k x) = exp2(-k*log2e*x))
            float f = 0.1818f  * exp2f(-3.2f    * L2E * x)
                    + 0.5099f  * exp2f(-0.9423f * L2E * x)
                    + 0.2802f  * exp2f(-0.4029f * L2E * x)
                    + 0.02817f * exp2f(-0.2016f * L2E * x);
            float phi = 0.5f * (__cosf(PI_F * __fdividef(d, rsum)) + 1.0f);
            float zif = (float)zi, zjf = (float)zj;
            float en  = __fdividef(f * phi * COUL * zif * zjf, d);
            atomicAdd(sc + seg, en);
        }
    }

    // scalar tail (n_edges not divisible by 4) — handled by first few threads
    int base = n4 << 2;
    int t = blockIdx.x * blockDim.x + threadIdx.x;
    if (t < rem) {
        int e = base + t;
        int i = __ldg(pair_idx + e);
        int j = __ldg(pair_idx + n_edges + e);
        if (i < j) {
            int pi = __ldg(g_packed + i);
            int pj = __ldg(g_packed + j);
            int zi = pi & 127, zj = pj & 127;
            float d = __ldg(d_ij + e);
            float rsum = s_rad[zi] + s_rad[zj];
            if (d < rsum) {
                int   seg = pi >> 7;
                float x   = d * (s_pow[zi] + s_pow[zj]) * INV_A;
                float f = 0.1818f  * exp2f(-3.2f    * L2E * x)
                        + 0.5099f  * exp2f(-0.9423f * L2E * x)
                        + 0.2802f  * exp2f(-0.4029f * L2E * x)
                        + 0.02817f * exp2f(-0.2016f * L2E * x);
                float phi = 0.5f * (__cosf(PI_F * __fdividef(d, rsum)) + 1.0f);
                float en  = __fdividef(f * phi * COUL * (float)zi * (float)zj, d);
                atomicAdd(sc + seg, en);
            }
        }
    }
}

__global__ void reduce_kernel(float* __restrict__ out, int n_seg) {
    int s = blockIdx.x * blockDim.x + threadIdx.x;
    if (s < n_seg) {
        float a = 0.0f;
        #pragma unroll
        for (int r = 0; r < REPL; r++) a += g_scratch[r * N_SEG_MAX + s];
        out[s] = a;
    }
}

extern "C" void kernel_launch(void* const* d_in, const int* in_sizes, int n_in,
                              void* d_out, int out_size) {
    const float* d_ij   = (const float*)d_in[0];
    const float* radii  = (const float*)d_in[1];
    const int*   pairs  = (const int*)d_in[2];
    const int*   zs     = (const int*)d_in[3];
    const int*   segs   = (const int*)d_in[4];

    int n_edges = in_sizes[0];
    int n_radii = in_sizes[1];
    int n_atoms = in_sizes[3];
    int n_seg   = out_size;

    // 1. zero the replicated scratch
    {
        int n = REPL * N_SEG_MAX;
        zero_scratch_kernel<<<(n + 255) / 256, 256>>>(n);
    }
    // 2. pack (seg, z) per atom
    pack_kernel<<<(n_atoms + 255) / 256, 256>>>(zs, segs, n_atoms);

    // 3. main edge kernel: 4 edges per thread
    {
        int n4 = n_edges >> 2;
        int threads = 256;
        int blocks = (n4 + threads - 1) / threads;
        if (blocks < 1) blocks = 1;
        edge_kernel<<<blocks, threads>>>(d_ij, radii, pairs, n_edges, n_radii);
    }

    // 4. reduce replicas into output
    reduce_kernel<<<(n_seg + 255) / 256, 256>>>((float*)d_out, n_seg);
}

// round 14
// speedup vs baseline: 1.0166x; 1.0024x over previous
#include <cuda_runtime.h>
#include <cuda_bf16.h>

// Inputs (metadata order):
//  d_in[0]: local_d_ij                 float32 [16,000,000]
//  d_in[1]: radii_table                float32 [97]
//  d_in[2]: local_pair_indices         int32   [2, 16,000,000] flattened
//  d_in[3]: atomic_numbers             int32   [1,000,000]
//  d_in[4]: atomic_subsystem_indices   int32   [1,000,000]
//  d_out  : per_system energies        float32 [10,000]

#define N_SEG_MAX   10000
#define N_ATOMS_MAX 1000000
#define REPL        16          // scratch replicas to spread atomic contention
#define ZTAB        128         // padded table size (z in 1..96)

static __device__ float g_scratch[REPL * N_SEG_MAX];
static __device__ int   g_packed[N_ATOMS_MAX];   // (seg << 7) | z

__global__ void pack_kernel(const int* __restrict__ z,
                            const int* __restrict__ seg, int n) {
    int i = blockIdx.x * blockDim.x + threadIdx.x;
    if (i < n) g_packed[i] = (seg[i] << 7) | z[i];
}

__global__ void zero_scratch_kernel(int n) {
    int i = blockIdx.x * blockDim.x + threadIdx.x;
    if (i < n) g_scratch[i] = 0.0f;
}

__global__ __launch_bounds__(256)
void edge_kernel(const float* __restrict__ d_ij,
                 const float* __restrict__ radii,
                 const int*   __restrict__ pair_idx,
                 int n_edges, int n_radii) {
    __shared__ float s_rad[ZTAB];
    __shared__ float s_pow[ZTAB];   // z^0.23

    for (int t = threadIdx.x; t < ZTAB; t += blockDim.x) {
        s_rad[t] = (t < n_radii) ? radii[t] : 0.0f;
        s_pow[t] = powf((float)t, 0.23f);
    }
    __syncthreads();

    const double A_PREF_D = 0.8854 * 0.0529177210903;
    const float  INV_A    = (float)(1.0 / A_PREF_D);
    const float  COUL     = 138.9354576f;
    const float  PI_F     = 3.14159265358979f;
    const float  L2E      = 1.44269504088896f;   // log2(e)

    const int4*   ii4 = (const int4*)pair_idx;
    const int4*   jj4 = (const int4*)(pair_idx + n_edges);
    const float4* dd4 = (const float4*)d_ij;

    int n4  = n_edges >> 2;
    int rem = n_edges - (n4 << 2);
    int stride = gridDim.x * blockDim.x;

    // replica: mix block and warp so concurrent warps hit different replicas
    int rep = (blockIdx.x * 8 + (threadIdx.x >> 5)) & (REPL - 1);
    float* sc = g_scratch + rep * N_SEG_MAX;

    for (int e4 = blockIdx.x * blockDim.x + threadIdx.x; e4 < n4; e4 += stride) {
        int4   vi = __ldg(ii4 + e4);
        int4   vj = __ldg(jj4 + e4);
        float4 vd = __ldg(dd4 + e4);

        int   is[4] = {vi.x, vi.y, vi.z, vi.w};
        int   js[4] = {vj.x, vj.y, vj.z, vj.w};
        float ds[4] = {vd.x, vd.y, vd.z, vd.w};

        #pragma unroll
        for (int k = 0; k < 4; k++) {
            int i = is[k], j = js[k];
            if (i >= j) continue;               // mask: idx_i < idx_j
            int pi = __ldg(g_packed + i);
            int pj = __ldg(g_packed + j);
            int zi = pi & 127;
            int zj = pj & 127;
            float d = ds[k];
            float rsum = s_rad[zi] + s_rad[zj];
            if (d >= rsum) continue;            // phi == 0 -> energy == 0

            int   seg = pi >> 7;
            float x   = d * (s_pow[zi] + s_pow[zj]) * INV_A;
            // f = sum of 4 exponentials (exp(-k x) = exp2(-k*log2e*x))
            float f = 0.1818f  * exp2f(-3.2f    * L2E * x)
                    + 0.5099f  * exp2f(-0.9423f * L2E * x)
                    + 0.2802f  * exp2f(-0.4029f * L2E * x)
                    + 0.02817f * exp2f(-0.2016f * L2E * x);
            float phi = 0.5f * (__cosf(PI_F * __fdividef(d, rsum)) + 1.0f);
            float zif = (float)zi, zjf = (float)zj;
            float en  = __fdividef(f * phi * COUL * zif * zjf, d);
            atomicAdd(sc + seg, en);
        }
    }

    // scalar tail (n_edges not divisible by 4) — handled by first few threads
    int base = n4 << 2;
    int t = blockIdx.x * blockDim.x + threadIdx.x;
    if (t < rem) {
        int e = base + t;
        int i = __ldg(pair_idx + e);
        int j = __ldg(pair_idx + n_edges + e);
        if (i < j) {
            int pi = __ldg(g_packed + i);
            int pj = __ldg(g_packed + j);
            int zi = pi & 127, zj = pj & 127;
            float d = __ldg(d_ij + e);
            float rsum = s_rad[zi] + s_rad[zj];
            if (d < rsum) {
                int   seg = pi >> 7;
                float x   = d * (s_pow[zi] + s_pow[zj]) * INV_A;
                float f = 0.1818f  * exp2f(-3.2f    * L2E * x)
                        + 0.5099f  * exp2f(-0.9423f * L2E * x)
                        + 0.2802f  * exp2f(-0.4029f * L2E * x)
                        + 0.02817f * exp2f(-0.2016f * L2E * x);
                float phi = 0.5f * (__cosf(PI_F * __fdividef(d, rsum)) + 1.0f);
                float en  = __fdividef(f * phi * COUL * (float)zi * (float)zj, d);
                atomicAdd(sc + seg, en);
            }
        }
    }
}

__global__ void reduce_kernel(float* __restrict__ out, int n_seg) {
    int s = blockIdx.x * blockDim.x + threadIdx.x;
    if (s < n_seg) {
        float a = 0.0f;
        #pragma unroll
        for (int r = 0; r < REPL; r++) a += g_scratch[r * N_SEG_MAX + s];
        out[s] = a;
    }
}

extern "C" void kernel_launch(void* const* d_in, const int* in_sizes, int n_in,
                              void* d_out, int out_size) {
    const float* d_ij   = (const float*)d_in[0];
    const float* radii  = (const float*)d_in[1];
    const int*   pairs  = (const int*)d_in[2];
    const int*   zs     = (const int*)d_in[3];
    const int*   segs   = (const int*)d_in[4];

    int n_edges = in_sizes[0];
    int n_radii = in_sizes[1];
    int n_atoms = in_sizes[3];
    int n_seg   = out_size;

    // 1. zero the replicated scratch
    {
        int n = REPL * N_SEG_MAX;
        zero_scratch_kernel<<<(n + 255) / 256, 256>>>(n);
    }
    // 2. pack (seg, z) per atom
    pack_kernel<<<(n_atoms + 255) / 256, 256>>>(zs, segs, n_atoms);

    // 3. main edge kernel: 4 edges per thread
    {
        int n4 = n_edges >> 2;
        int threads = 256;
        int blocks = (n4 + threads - 1) / threads;
        if (blocks < 1) blocks = 1;
        edge_kernel<<<blocks, threads>>>(d_ij, radii, pairs, n_edges, n_radii);
    }

    // 4. reduce replicas into output
    reduce_kernel<<<(n_seg + 255) / 256, 256>>>((float*)d_out, n_seg);
}

// round 15
// speedup vs baseline: 1.0173x; 1.0007x over previous
#include <cuda_runtime.h>
#include <cuda_bf16.h>

// Inputs (metadata order):
//  d_in[0]: local_d_ij                 float32 [16,000,000]
//  d_in[1]: radii_table                float32 [97]
//  d_in[2]: local_pair_indices         int32   [2, 16,000,000] flattened
//  d_in[3]: atomic_numbers             int32   [1,000,000]
//  d_in[4]: atomic_subsystem_indices   int32   [1,000,000]
//  d_out  : per_system energies        float32 [10,000]

#define N_SEG_MAX   10000
#define N_ATOMS_MAX 1000000
#define REPL        16          // scratch replicas to spread atomic contention
#define ZTAB        128         // padded table size (z in 1..96)

static __device__ float g_scratch[REPL * N_SEG_MAX];
static __device__ int   g_packed[N_ATOMS_MAX];   // (seg << 7) | z

__global__ void pack_kernel(const int* __restrict__ z,
                            const int* __restrict__ seg, int n) {
    int i = blockIdx.x * blockDim.x + threadIdx.x;
    if (i < n) g_packed[i] = (seg[i] << 7) | z[i];
}

__global__ void zero_scratch_kernel(int n) {
    int i = blockIdx.x * blockDim.x + threadIdx.x;
    if (i < n) g_scratch[i] = 0.0f;
}

__global__ __launch_bounds__(256)
void edge_kernel(const float* __restrict__ d_ij,
                 const float* __restrict__ radii,
                 const int*   __restrict__ pair_idx,
                 int n_edges, int n_radii) {
    __shared__ float s_rad[ZTAB];
    __shared__ float s_pow[ZTAB];   // z^0.23

    for (int t = threadIdx.x; t < ZTAB; t += blockDim.x) {
        s_rad[t] = (t < n_radii) ? radii[t] : 0.0f;
        s_pow[t] = powf((float)t, 0.23f);
    }
    __syncthreads();

    const double A_PREF_D = 0.8854 * 0.0529177210903;
    const float  INV_A    = (float)(1.0 / A_PREF_D);
    const float  COUL     = 138.9354576f;
    const float  PI_F     = 3.14159265358979f;
    const float  L2E      = 1.44269504088896f;   // log2(e)

    const int4*   ii4 = (const int4*)pair_idx;
    const int4*   jj4 = (const int4*)(pair_idx + n_edges);
    const float4* dd4 = (const float4*)d_ij;

    int n4  = n_edges >> 2;
    int rem = n_edges - (n4 << 2);
    int stride = gridDim.x * blockDim.x;

    // replica: mix block and warp so concurrent warps hit different replicas
    int rep = (blockIdx.x * 8 + (threadIdx.x >> 5)) & (REPL - 1);
    float* sc = g_scratch + rep * N_SEG_MAX;

    for (int e4 = blockIdx.x * blockDim.x + threadIdx.x; e4 < n4; e4 += stride) {
        int4   vi = __ldg(ii4 + e4);
        int4   vj = __ldg(jj4 + e4);
        float4 vd = __ldg(dd4 + e4);

        int   is[4] = {vi.x, vi.y, vi.z, vi.w};
        int   js[4] = {vj.x, vj.y, vj.z, vj.w};
        float ds[4] = {vd.x, vd.y, vd.z, vd.w};

        #pragma unroll
        for (int k = 0; k < 4; k++) {
            int i = is[k], j = js[k];
            if (i >= j) continue;               // mask: idx_i < idx_j
            int pi = __ldg(g_packed + i);
            int pj = __ldg(g_packed + j);
            int zi = pi & 127;
            int zj = pj & 127;
            float d = ds[k];
            float rsum = s_rad[zi] + s_rad[zj];
            if (d >= rsum) continue;            // phi == 0 -> energy == 0

            int   seg = pi >> 7;
            float x   = d * (s_pow[zi] + s_pow[zj]) * INV_A;
            // f = sum of 4 exponentials (exp(-k x) = exp2(-k*log2e*x))
            float f = 0.1818f  * exp2f(-3.2f    * L2E * x)
                    + 0.5099f  * exp2f(-0.9423f * L2E * x)
                    + 0.2802f  * exp2f(-0.4029f * L2E * x)
                    + 0.02817f * exp2f(-0.2016f * L2E * x);
            float phi = 0.5f * (__cosf(PI_F * __fdividef(d, rsum)) + 1.0f);
            float zif = (float)zi, zjf = (float)zj;
            float en  = __fdividef(f * phi * COUL * zif * zjf, d);
            atomicAdd(sc + seg, en);
        }
    }

    // scalar tail (n_edges not divisible by 4) — handled by first few threads
    int base = n4 << 2;
    int t = blockIdx.x * blockDim.x + threadIdx.x;
    if (t < rem) {
        int e = base + t;
        int i = __ldg(pair_idx + e);
        int j = __ldg(pair_idx + n_edges + e);
        if (i < j) {
            int pi = __ldg(g_packed + i);
            int pj = __ldg(g_packed + j);
            int zi = pi & 127, zj = pj & 127;
            float d = __ldg(d_ij + e);
            float rsum = s_rad[zi] + s_rad[zj];
            if (d < rsum) {
                int   seg = pi >> 7;
                float x   = d * (s_pow[zi] + s_pow[zj]) * INV_A;
                float f = 0.1818f  * exp2f(-3.2f    * L2E * x)
                        + 0.5099f  * exp2f(-0.9423f * L2E * x)
                        + 0.2802f  * exp2f(-0.4029f * L2E * x)
                        + 0.02817f * exp2f(-0.2016f * L2E * x);
                float phi = 0.5f * (__cosf(PI_F * __fdividef(d, rsum)) + 1.0f);
                float en  = __fdividef(f * phi * COUL * (float)zi * (float)zj, d);
                atomicAdd(sc + seg, en);
            }
        }
    }
}

__global__ void reduce_kernel(float* __restrict__ out, int n_seg) {
    int s = blockIdx.x * blockDim.x + threadIdx.x;
    if (s < n_seg) {
        float a = 0.0f;
        #pragma unroll
        for (int r = 0; r < REPL; r++) a += g_scratch[r * N_SEG_MAX + s];
        out[s] = a;
    }
}

extern "C" void kernel_launch(void* const* d_in, const int* in_sizes, int n_in,
                              void* d_out, int out_size) {
    const float* d_ij   = (const float*)d_in[0];
    const float* radii  = (const float*)d_in[1];
    const int*   pairs  = (const int*)d_in[2];
    const int*   zs     = (const int*)d_in[3];
    const int*   segs   = (const int*)d_in[4];

    int n_edges = in_sizes[0];
    int n_radii = in_sizes[1];
    int n_atoms = in_sizes[3];
    int n_seg   = out_size;

    // 1. zero the replicated scratch
    {
        int n = REPL * N_SEG_MAX;
        zero_scratch_kernel<<<(n + 255) / 256, 256>>>(n);
    }
    // 2. pack (seg, z) per atom
    pack_kernel<<<(n_atoms + 255) / 256, 256>>>(zs, segs, n_atoms);

    // 3. main edge kernel: 4 edges per thread
    {
        int n4 = n_edges >> 2;
        int threads = 256;
        int blocks = (n4 + threads - 1) / threads;
        if (blocks < 1) blocks = 1;
        edge_kernel<<<blocks, threads>>>(d_ij, radii, pairs, n_edges, n_radii);
    }

    // 4. reduce replicas into output
    reduce_kernel<<<(n_seg + 255) / 256, 256>>>((float*)d_out, n_seg);
}

// round 16
// speedup vs baseline: 1.0176x; 1.0003x over previous
#include <cuda_runtime.h>
#include <cuda_bf16.h>

// Inputs (metadata order):
//  d_in[0]: local_d_ij                 float32 [16,000,000]
//  d_in[1]: radii_table                float32 [97]
//  d_in[2]: local_pair_indices         int32   [2, 16,000,000] flattened
//  d_in[3]: atomic_numbers             int32   [1,000,000]
//  d_in[4]: atomic_subsystem_indices   int32   [1,000,000]
//  d_out  : per_system energies        float32 [10,000]

#define N_SEG_MAX   10000
#define N_ATOMS_MAX 1000000
#define REPL        16          // scratch replicas to spread atomic contention
#define ZTAB        128         // padded table size (z in 1..96)

static __device__ float g_scratch[REPL * N_SEG_MAX];
static __device__ int   g_packed[N_ATOMS_MAX];   // (seg << 7) | z

__global__ void pack_kernel(const int* __restrict__ z,
                            const int* __restrict__ seg, int n) {
    int i = blockIdx.x * blockDim.x + threadIdx.x;
    if (i < n) g_packed[i] = (seg[i] << 7) | z[i];
}

__global__ void zero_scratch_kernel(int n) {
    int i = blockIdx.x * blockDim.x + threadIdx.x;
    if (i < n) g_scratch[i] = 0.0f;
}

__global__ __launch_bounds__(256)
void edge_kernel(const float* __restrict__ d_ij,
                 const float* __restrict__ radii,
                 const int*   __restrict__ pair_idx,
                 int n_edges, int n_radii) {
    __shared__ float s_rad[ZTAB];
    __shared__ float s_pow[ZTAB];   // z^0.23

    for (int t = threadIdx.x; t < ZTAB; t += blockDim.x) {
        s_rad[t] = (t < n_radii) ? radii[t] : 0.0f;
        s_pow[t] = powf((float)t, 0.23f);
    }
    __syncthreads();

    const double A_PREF_D = 0.8854 * 0.0529177210903;
    const float  INV_A    = (float)(1.0 / A_PREF_D);
    const float  COUL     = 138.9354576f;
    const float  PI_F     = 3.14159265358979f;
    const float  L2E      = 1.44269504088896f;   // log2(e)

    const int4*   ii4 = (const int4*)pair_idx;
    const int4*   jj4 = (const int4*)(pair_idx + n_edges);
    const float4* dd4 = (const float4*)d_ij;

    int n4  = n_edges >> 2;
    int rem = n_edges - (n4 << 2);
    int stride = gridDim.x * blockDim.x;

    // replica: mix block and warp so concurrent warps hit different replicas
    int rep = (blockIdx.x * 8 + (threadIdx.x >> 5)) & (REPL - 1);
    float* sc = g_scratch + rep * N_SEG_MAX;

    for (int e4 = blockIdx.x * blockDim.x + threadIdx.x; e4 < n4; e4 += stride) {
        int4   vi = __ldg(ii4 + e4);
        int4   vj = __ldg(jj4 + e4);
        float4 vd = __ldg(dd4 + e4);

        int   is[4] = {vi.x, vi.y, vi.z, vi.w};
        int   js[4] = {vj.x, vj.y, vj.z, vj.w};
        float ds[4] = {vd.x, vd.y, vd.z, vd.w};

        #pragma unroll
        for (int k = 0; k < 4; k++) {
            int i = is[k], j = js[k];
            if (i >= j) continue;               // mask: idx_i < idx_j
            int pi = __ldg(g_packed + i);
            int pj = __ldg(g_packed + j);
            int zi = pi & 127;
            int zj = pj & 127;
            float d = ds[k];
            float rsum = s_rad[zi] + s_rad[zj];
            if (d >= rsum) continue;            // phi == 0 -> energy == 0

            int   seg = pi >> 7;
            float x   = d * (s_pow[zi] + s_pow[zj]) * INV_A;
            // f = sum of 4 exponentials (exp(-k x) = exp2(-k*log2e*x))
            float f = 0.1818f  * exp2f(-3.2f    * L2E * x)
                    + 0.5099f  * exp2f(-0.9423f * L2E * x)
                    + 0.2802f  * exp2f(-0.4029f * L2E * x)
                    + 0.02817f * exp2f(-0.2016f * L2E * x);
            float phi = 0.5f * (__cosf(PI_F * __fdividef(d, rsum)) + 1.0f);
            float zif = (float)zi, zjf = (float)zj;
            float en  = __fdividef(f * phi * COUL * zif * zjf, d);
            atomicAdd(sc + seg, en);
        }
    }

    // scalar tail (n_edges not divisible by 4) — handled by first few threads
    int base = n4 << 2;
    int t = blockIdx.x * blockDim.x + threadIdx.x;
    if (t < rem) {
        int e = base + t;
        int i = __ldg(pair_idx + e);
        int j = __ldg(pair_idx + n_edges + e);
        if (i < j) {
            int pi = __ldg(g_packed + i);
            int pj = __ldg(g_packed + j);
            int zi = pi & 127, zj = pj & 127;
            float d = __ldg(d_ij + e);
            float rsum = s_rad[zi] + s_rad[zj];
            if (d < rsum) {
                int   seg = pi >> 7;
                float x   = d * (s_pow[zi] + s_pow[zj]) * INV_A;
                float f = 0.1818f  * exp2f(-3.2f    * L2E * x)
                        + 0.5099f  * exp2f(-0.9423f * L2E * x)
                        + 0.2802f  * exp2f(-0.4029f * L2E * x)
                        + 0.02817f * exp2f(-0.2016f * L2E * x);
                float phi = 0.5f * (__cosf(PI_F * __fdividef(d, rsum)) + 1.0f);
                float en  = __fdividef(f * phi * COUL * (float)zi * (float)zj, d);
                atomicAdd(sc + seg, en);
            }
        }
    }
}

__global__ void reduce_kernel(float* __restrict__ out, int n_seg) {
    int s = blockIdx.x * blockDim.x + threadIdx.x;
    if (s < n_seg) {
        float a = 0.0f;
        #pragma unroll
        for (int r = 0; r < REPL; r++) a += g_scratch[r * N_SEG_MAX + s];
        out[s] = a;
    }
}

extern "C" void kernel_launch(void* const* d_in, const int* in_sizes, int n_in,
                              void* d_out, int out_size) {
    const float* d_ij   = (const float*)d_in[0];
    const float* radii  = (const float*)d_in[1];
    const int*   pairs  = (const int*)d_in[2];
    const int*   zs     = (const int*)d_in[3];
    const int*   segs   = (const int*)d_in[4];

    int n_edges = in_sizes[0];
    int n_radii = in_sizes[1];
    int n_atoms = in_sizes[3];
    int n_seg   = out_size;

    // 1. zero the replicated scratch
    {
        int n = REPL * N_SEG_MAX;
        zero_scratch_kernel<<<(n + 255) / 256, 256>>>(n);
    }
    // 2. pack (seg, z) per atom
    pack_kernel<<<(n_atoms + 255) / 256, 256>>>(zs, segs, n_atoms);

    // 3. main edge kernel: 4 edges per thread
    {
        int n4 = n_edges >> 2;
        int threads = 256;
        int blocks = (n4 + threads - 1) / threads;
        if (blocks < 1) blocks = 1;
        edge_kernel<<<blocks, threads>>>(d_ij, radii, pairs, n_edges, n_radii);
    }

    // 4. reduce replicas into output
    reduce_kernel<<<(n_seg + 255) / 256, 256>>>((float*)d_out, n_seg);
}